// round 17
// baseline (speedup 1.0000x reference)
#include <cuda_runtime.h>
#include <cstdint>
#include <math.h>

#define NTOK 16384
#define DM 512
#define DH 2048
#define NE 8
#define NASN (2*NTOK)          // 32768 assignments
#define CAP (NASN + NE*128)    // 33792 (each expert padded to 128)
#define NTILES (CAP/128)       // 264 row tiles

// ---- scratch (device globals; fp16 data held in uint32_t arrays ONLY) ----
__device__ int      g_cnt[NE];
__device__ int      g_off[NE+1];
__device__ int      g_tile_e[NTILES];
__device__ int      g_as_e[NASN];
__device__ int      g_as_r[NASN];
__device__ float    g_as_w[NASN];
__device__ int      g_tokpos[NASN];
__device__ int      g_extok[CAP];
__device__ uint32_t g_xp[(size_t)NTOK*(DM/2)];      // x as f16 pairs: [t][kp=256]
__device__ uint32_t g_w1t[(size_t)NE*DH*(DM/2)];    // W1^T pairs: [e][n=2048][kp=256]
__device__ uint32_t g_w2t[(size_t)NE*DM*(DH/2)];    // W2^T pairs: [e][n=512][kp=1024]
__device__ uint32_t g_hp[(size_t)CAP*(DH/2)];       // hidden f16 pairs: [row][kp=1024]
__device__ float    g_ybuf[(size_t)CAP*DM];

// ---- helpers ----
__device__ __forceinline__ uint32_t pk(float lo, float hi){
    uint32_t r; asm("cvt.rn.f16x2.f32 %0, %1, %2;" : "=r"(r) : "f"(hi), "f"(lo));
    return r;
}
__device__ __forceinline__ void mma16(float* c, const uint32_t* a, const uint32_t* b){
    asm volatile(
      "mma.sync.aligned.m16n8k16.row.col.f32.f16.f16.f32 "
      "{%0,%1,%2,%3},{%4,%5,%6,%7},{%8,%9},{%0,%1,%2,%3};"
      : "+f"(c[0]), "+f"(c[1]), "+f"(c[2]), "+f"(c[3])
      : "r"(a[0]), "r"(a[1]), "r"(a[2]), "r"(a[3]), "r"(b[0]), "r"(b[1]));
}
__device__ __forceinline__ void ldsm4(uint32_t* r, uint32_t addr){
    asm volatile("ldmatrix.sync.aligned.m8n8.x4.shared.b16 {%0,%1,%2,%3}, [%4];"
        : "=r"(r[0]), "=r"(r[1]), "=r"(r[2]), "=r"(r[3]) : "r"(addr));
}
__device__ __forceinline__ float gelu_exact(float x){
    return 0.5f * x * (1.0f + erff(x * 0.7071067811865476f));
}

// ---- launch 1: init + transpose-and-pack W1,W2 to [e][n][kp] fp16 pairs ----
// grid (64, 64, 16): z<8 -> W1 expert z (needs y<16, x<64); z>=8 -> W2 (y<64, x<16).
__global__ void k_tr(const float* __restrict__ W1, const float* __restrict__ W2){
    // fold in counter/pad-map init (blocks z=0, y=0 are always active W1 blocks)
    if (blockIdx.z == 0 && blockIdx.y == 0){
        int t = blockIdx.x * 256 + threadIdx.y * 32 + threadIdx.x;
        if (t < NE) g_cnt[t] = 0;
        for (int i = t; i < CAP; i += 64*256) g_extok[i] = -1;
    }
    bool isW1 = blockIdx.z < 8;
    if (isW1 ? (blockIdx.y >= 16) : (blockIdx.x >= 16)) return;
    int e = isW1 ? blockIdx.z : blockIdx.z - 8;
    int K = isW1 ? DM : DH;
    int N = isW1 ? DH : DM;
    const float* S = (isW1 ? W1 : W2) + (size_t)e * K * N;
    uint32_t* D = (isW1 ? g_w1t : g_w2t) + (size_t)e * N * (K/2);
    int k0 = blockIdx.y * 32, n0 = blockIdx.x * 32;
    __shared__ float s[32][33];
    int tx = threadIdx.x, ty = threadIdx.y;   // 32 x 8
    #pragma unroll
    for (int i = 0; i < 32; i += 8)
        s[ty+i][tx] = S[(size_t)(k0+ty+i)*N + n0 + tx];
    __syncthreads();
    int idx = ty*32 + tx;                     // 0..255
    #pragma unroll
    for (int j = 0; j < 2; j++){
        int q = idx + j*256;                  // 0..511
        int nn = q >> 4, pc = q & 15;
        D[(size_t)(n0+nn)*(K/2) + (k0 >> 1) + pc] = pk(s[2*pc][nn], s[2*pc+1][nn]);
    }
}

// ---- launch 2: router + x->f16 pair conversion (fused) ----
__global__ void k_router(const float* __restrict__ x, const float* __restrict__ Wg,
                         float* __restrict__ out_logits){
    {
        int base = blockIdx.x * 512;
        #pragma unroll
        for (int k = 0; k < 2; k++){
            int j = base + threadIdx.x + k*256;
            float4 v0 = ((const float4*)x)[2*j];
            float4 v1 = ((const float4*)x)[2*j + 1];
            uint4 u;
            u.x = pk(v0.x, v0.y); u.y = pk(v0.z, v0.w);
            u.z = pk(v1.x, v1.y); u.w = pk(v1.z, v1.w);
            ((uint4*)g_xp)[j] = u;
        }
    }
    __shared__ float sWg[NE*DM];
    for (int i = threadIdx.x; i < NE*DM; i += 256) sWg[i] = Wg[i];
    __syncthreads();
    int wid = threadIdx.x >> 5, lane = threadIdx.x & 31;
    int t = blockIdx.x * 8 + wid;
    const float* xr = x + (size_t)t * DM;
    float acc[NE];
    #pragma unroll
    for (int e = 0; e < NE; e++) acc[e] = 0.f;
    for (int i = lane; i < DM; i += 32){
        float xv = xr[i];
        #pragma unroll
        for (int e = 0; e < NE; e++) acc[e] += xv * sWg[e*DM + i];
    }
    #pragma unroll
    for (int e = 0; e < NE; e++){
        float v = acc[e];
        #pragma unroll
        for (int o = 16; o > 0; o >>= 1) v += __shfl_xor_sync(0xffffffffu, v, o);
        acc[e] = v;
    }
    if (lane == 0){
        #pragma unroll
        for (int e = 0; e < NE; e++) out_logits[(size_t)t*NE + e] = acc[e];
        int e0 = 0; float v0 = acc[0];
        #pragma unroll
        for (int e = 1; e < NE; e++) if (acc[e] > v0){ v0 = acc[e]; e0 = e; }
        int e1 = -1; float v1 = -3.4e38f;
        #pragma unroll
        for (int e = 0; e < NE; e++) if (e != e0 && acc[e] > v1){ v1 = acc[e]; e1 = e; }
        float ex = expf(v1 - v0);
        float s  = 1.0f + ex;
        float w0 = 1.0f / s, w1 = ex / s;
        int r0 = atomicAdd(&g_cnt[e0], 1);
        int r1 = atomicAdd(&g_cnt[e1], 1);
        g_as_e[2*t] = e0;   g_as_r[2*t] = r0;   g_as_w[2*t] = w0;
        g_as_e[2*t+1] = e1; g_as_r[2*t+1] = r1; g_as_w[2*t+1] = w1;
    }
}

// ---- launch 3: offsets + tile map + scatter (single block) ----
__global__ void k_offscat(){
    __shared__ int soff[NE+1];
    if (threadIdx.x == 0){
        int o = 0; soff[0] = 0;
        for (int e = 0; e < NE; e++){ o += (g_cnt[e] + 127) & ~127; soff[e+1] = o; }
    }
    __syncthreads();
    for (int i = threadIdx.x; i < NTILES; i += blockDim.x){
        int pos = i * 128, te = -1;
        for (int e = 0; e < NE; e++)
            if (pos >= soff[e] && pos < soff[e+1]) te = e;
        g_tile_e[i] = te;
    }
    if (threadIdx.x <= NE) g_off[threadIdx.x] = soff[threadIdx.x];
    for (int i = threadIdx.x; i < NASN; i += blockDim.x){
        int e = g_as_e[i];
        int pos = soff[e] + g_as_r[i];
        g_extok[pos] = i >> 1;
        g_tokpos[i] = pos;
    }
}

// ---- launches 4/5: fp16 GEMM, ldmatrix for BOTH A and B fragments ----
// 128 thr, 4 warps (2x2), warp tile 64x64, BK=64 halves, 3-stage cp.async (96KB).
// A smem: 128 rows x 32 pair-cols (xor swizzle). B smem: 128 n-rows x 32 pair-cols (same).
// FIRST: A = gather g_xp rows (K=512h), B = g_w1t, C = g_hp (gelu->f16 pairs)
// !FIRST: A = g_hp rows (K=2048h),      B = g_w2t, C = g_ybuf (fp32)
template<bool FIRST>
__global__ __launch_bounds__(128)
void k_gemm(){
    constexpr int KP  = FIRST ? (DM/2) : (DH/2);   // pair stride for BOTH A rows and B n-rows
    constexpr int NIT = FIRST ? (DM/64) : (DH/64); // 8 / 32 iters
    extern __shared__ uint32_t smem[];   // A: 3*4096 u32, B: 3*4096 u32 (96KB)
    int tile = blockIdx.y;
    int e = g_tile_e[tile];
    if (e < 0) return;
    int n0 = blockIdx.x * 128;
    int tid = threadIdx.x, lane = tid & 31, wid = tid >> 5;
    int g = lane >> 2, t4 = lane & 3;
    int wm = wid & 1, wn = wid >> 1;
    uint32_t smem_b;
    asm("{ .reg .u64 t; cvta.to.shared.u64 t, %1; cvt.u32.u64 %0, t; }"
        : "=r"(smem_b) : "l"(smem));

    const uint32_t* __restrict__ Wp = (FIRST ? g_w1t : g_w2t) + (size_t)e * (FIRST ? DH : DM) * KP;
    const uint32_t* __restrict__ Ab = FIRST ? g_xp : (g_hp + (size_t)tile * 128 * KP);

    int tokr[8];
    if (FIRST){
        #pragma unroll
        for (int i = 0; i < 8; i++)
            tokr[i] = g_extok[tile*128 + (tid >> 3) + i*16];
    }
    int rA0 = tid >> 3, jA = tid & 7;     // staging: row, 16B-chunk (A and B identical)

    // stage `idx` covers pair-cols [idx*32, idx*32+32)
    auto issue = [&](int s, int idx){
        uint32_t ab = smem_b + s * 16384;
        uint32_t bb = smem_b + 49152 + s * 16384;
        int kp = idx * 32;
        #pragma unroll
        for (int i = 0; i < 8; i++){
            int r = rA0 + i*16;
            uint32_t dst = ab + ((r*32 + ((jA ^ (r & 7)) << 2)) << 2);
            const uint32_t* src; int sz = 16;
            if (FIRST){
                int tok = tokr[i];
                src = Ab + (size_t)(tok < 0 ? 0 : tok) * KP + kp + (jA << 2);
                sz = (tok < 0) ? 0 : 16;
            } else {
                src = Ab + (size_t)r * KP + kp + (jA << 2);
            }
            asm volatile("cp.async.cg.shared.global [%0], [%1], 16, %2;"
                         :: "r"(dst), "l"(src), "r"(sz));
        }
        #pragma unroll
        for (int i = 0; i < 8; i++){
            int r = rA0 + i*16;                        // n-row of B^T tile
            uint32_t dst = bb + ((r*32 + ((jA ^ (r & 7)) << 2)) << 2);
            const uint32_t* src = Wp + (size_t)(n0 + r) * KP + kp + (jA << 2);
            asm volatile("cp.async.cg.shared.global [%0], [%1], 16, %2;"
                         :: "r"(dst), "l"(src), "r"(16));
        }
    };

    float acc[4][8][4];
    #pragma unroll
    for (int im = 0; im < 4; im++)
        #pragma unroll
        for (int jn = 0; jn < 8; jn++)
            #pragma unroll
            for (int q = 0; q < 4; q++) acc[im][jn][q] = 0.f;

    issue(0, 0); asm volatile("cp.async.commit_group;" ::: "memory");
    issue(1, 1); asm volatile("cp.async.commit_group;" ::: "memory");

    // ldmatrix addressing (validated A mapping; B is the mirrored assignment).
    int lo = lane & 7;
    // A: matrices (rb,c0)(rb+8,c0)(rb,c1)(rb+8,c1): octet=(L>>3)&1, chunk-sel=L>>4
    uint32_t aRow = (uint32_t)((wm*64 + ((lane >> 3) & 1)*8 + lo) * 128);
    // B: matrices (nb,c0)(nb,c1)(nb+8,c0)(nb+8,c1): chunk-sel=(L>>3)&1, octet=(L>>4)&1
    uint32_t bRow = (uint32_t)((wn*64 + ((lane >> 4) & 1)*8 + lo) * 128);
    uint32_t cOffA[4], cOffB[4];
    #pragma unroll
    for (int ks = 0; ks < 4; ks++){
        cOffA[ks] = (uint32_t)(((2*ks + (lane >> 4)) ^ lo) << 4);
        cOffB[ks] = (uint32_t)(((2*ks + ((lane >> 3) & 1)) ^ lo) << 4);
    }

    for (int it = 0; it < NIT; ++it){
        asm volatile("cp.async.wait_group 1;" ::: "memory");
        __syncthreads();
        if (it + 2 < NIT) issue((it + 2) % 3, it + 2);
        asm volatile("cp.async.commit_group;" ::: "memory");
        uint32_t abase = smem_b + (it % 3) * 16384;
        uint32_t bbase = smem_b + 49152 + (it % 3) * 16384;
        #pragma unroll
        for (int ks = 0; ks < 4; ks++){
            uint32_t a[4][4];
            #pragma unroll
            for (int im = 0; im < 4; im++)
                ldsm4(a[im], abase + aRow + (uint32_t)(im*2048) + cOffA[ks]);
            uint32_t bf[4][4];   // bf[p] = {b[2p][0], b[2p][1], b[2p+1][0], b[2p+1][1]}
            #pragma unroll
            for (int p = 0; p < 4; p++)
                ldsm4(bf[p], bbase + bRow + (uint32_t)(p*2048) + cOffB[ks]);
            #pragma unroll
            for (int im = 0; im < 4; im++)
                #pragma unroll
                for (int jn = 0; jn < 8; jn++)
                    mma16(acc[im][jn], a[im], &bf[jn >> 1][(jn & 1) * 2]);
        }
    }

    // epilogue
    #pragma unroll
    for (int im = 0; im < 4; im++){
        int r = wm*64 + im*16 + g;
        #pragma unroll
        for (int jn = 0; jn < 8; jn++){
            int c = n0 + wn*64 + jn*8 + (t4 << 1);   // even
            if (FIRST){
                uint32_t* Ch = g_hp + (size_t)tile * 128 * (DH/2);
                int cp = c >> 1;
                Ch[(size_t)r * (DH/2) + cp] =
                    pk(gelu_exact(acc[im][jn][0]), gelu_exact(acc[im][jn][1]));
                Ch[(size_t)(r + 8) * (DH/2) + cp] =
                    pk(gelu_exact(acc[im][jn][2]), gelu_exact(acc[im][jn][3]));
            } else {
                float* Cf = g_ybuf + (size_t)tile * 128 * DM;
                *(float2*)(Cf + (size_t)r * DM + c)       = make_float2(acc[im][jn][0], acc[im][jn][1]);
                *(float2*)(Cf + (size_t)(r + 8) * DM + c) = make_float2(acc[im][jn][2], acc[im][jn][3]);
            }
        }
    }
}

// ---- launch 6: combine ----
__global__ void k_combine(float* __restrict__ out){
    int idx = blockIdx.x * 256 + threadIdx.x;
    int t = idx >> 7, d4 = idx & 127;
    int p0 = g_tokpos[2*t], p1 = g_tokpos[2*t + 1];
    float w0 = g_as_w[2*t], w1 = g_as_w[2*t + 1];
    float4 y0 = *(const float4*)(g_ybuf + (size_t)p0*DM + d4*4);
    float4 y1 = *(const float4*)(g_ybuf + (size_t)p1*DM + d4*4);
    float4 o;
    o.x = w0*y0.x + w1*y1.x;
    o.y = w0*y0.y + w1*y1.y;
    o.z = w0*y0.z + w1*y1.z;
    o.w = w0*y0.w + w1*y1.w;
    *(float4*)(out + (size_t)t*DM + d4*4) = o;
}

extern "C" void kernel_launch(void* const* d_in, const int* in_sizes, int n_in,
                              void* d_out, int out_size){
    const float* x  = (const float*)d_in[0];   // [16384, 512]
    const float* Wg = (const float*)d_in[1];   // [8, 512]
    const float* W1 = (const float*)d_in[2];   // [8, 512, 2048]
    const float* W2 = (const float*)d_in[3];   // [8, 2048, 512]
    float* out = (float*)d_out;                // out [T,512] then logits [T,8]

    const int SMEM = 98304;
    cudaFuncSetAttribute(k_gemm<true>,  cudaFuncAttributeMaxDynamicSharedMemorySize, SMEM);
    cudaFuncSetAttribute(k_gemm<false>, cudaFuncAttributeMaxDynamicSharedMemorySize, SMEM);

    k_tr<<<dim3(64, 64, 16), dim3(32, 8)>>>(W1, W2);         // launch 1 (init + W^T pack)
    k_router<<<NTOK/8, 256>>>(x, Wg, out + (size_t)NTOK*DM); // launch 2 (+x cvt)
    k_offscat<<<1, 1024>>>();                                // launch 3
    k_gemm<true><<<dim3(DH/128, NTILES), 128, SMEM>>>();     // launch 4 <- ncu lands here
    k_gemm<false><<<dim3(DM/128, NTILES), 128, SMEM>>>();    // launch 5
    k_combine<<<(NTOK*128)/256, 256>>>(out);                 // launch 6
}